// round 9
// baseline (speedup 1.0000x reference)
#include <cuda_runtime.h>
#include <cuda_bf16.h>
#include <math.h>
#include <stdint.h>

// ===========================================================================
// CBTree B=4, L=9, d=256.
// h_par = tanh(G @ B^T + v),  G=[gl|gr] (M x 512),  B=[Wl|Wr] (256 x 512).
//   gl = c0 + (2/3)c1 + (1/3)c2 ;  gr = (1/3)c1 + (2/3)c2 + c3
// n_par>=1024: bf16 hi/lo 3-pass HMMA, CTA 64x128, cp.async-pipelined fill.
//   Mid levels K-split over blockIdx.z with fused last-CTA reduce (counter).
// n_par<=256: fp32 SIMT, grid n_par*8.
// ===========================================================================

#define MTILE 64
#define NTILE 128

#define ST_A_HI 0
#define ST_A_LO 4096
#define ST_B_HI 8192
#define ST_B_LO 16384
#define STAGE   24576
#define SMEM_REQ (2 * STAGE)  // 48 KB

// swizzled byte offset of 16B block (row, cblk) in a 64B-row tile
#define SW(r, cb) ((uint32_t)((r) * 64 + (((cb) ^ (((r) >> 1) & 3)) << 4)))

// Scratch (__device__ globals: allocation-free rule)
__device__ float g_h0[16384 * 256];      // 16 MB ping
__device__ float g_h1[16384 * 256];      // 16 MB pong
__device__ float g_part[2097152];        // 8 MB K-split partials
__device__ int   g_cnt[256];             // per-tile arrival counters (self-reset)
__device__ uint4 g_Bhi[256 * 512 / 8];   // bf16 [256][512] hi of [Wl|Wr]
__device__ uint4 g_Blo[256 * 512 / 8];   // bf16 [256][512] lo

// ---------------------------------------------------------------------------
__device__ __forceinline__ uint32_t smem_u32(const void* p) {
    uint32_t a;
    asm("{ .reg .u64 t; cvta.to.shared.u64 t, %1; cvt.u32.u64 %0, t; }"
        : "=r"(a) : "l"(p));
    return a;
}
__device__ __forceinline__ void ldsm_x4(uint32_t* r, uint32_t addr) {
    asm volatile("ldmatrix.sync.aligned.m8n8.x4.shared.b16 {%0,%1,%2,%3}, [%4];"
                 : "=r"(r[0]), "=r"(r[1]), "=r"(r[2]), "=r"(r[3]) : "r"(addr));
}
__device__ __forceinline__ void mma16816(float* d, const uint32_t* a,
                                         const uint32_t* b) {
    asm volatile(
        "mma.sync.aligned.m16n8k16.row.col.f32.bf16.bf16.f32 "
        "{%0,%1,%2,%3}, {%4,%5,%6,%7}, {%8,%9}, {%0,%1,%2,%3};"
        : "+f"(d[0]), "+f"(d[1]), "+f"(d[2]), "+f"(d[3])
        : "r"(a[0]), "r"(a[1]), "r"(a[2]), "r"(a[3]), "r"(b[0]), "r"(b[1]));
}
__device__ __forceinline__ void cp_async16(uint32_t dst, const void* src) {
    asm volatile("cp.async.cg.shared.global [%0], [%1], 16;"
                 :: "r"(dst), "l"(src) : "memory");
}
#define CP_COMMIT() asm volatile("cp.async.commit_group;" ::: "memory")
#define CP_WAIT0()  asm volatile("cp.async.wait_group 0;" ::: "memory")

__device__ __forceinline__ void split2(float x, float y, uint32_t& hi, uint32_t& lo) {
    __nv_bfloat16 hx = __float2bfloat16(x);
    __nv_bfloat16 hy = __float2bfloat16(y);
    float rx = x - __bfloat162float(hx);
    float ry = y - __bfloat162float(hy);
    hi = (uint32_t)__bfloat16_as_ushort(hx) |
         ((uint32_t)__bfloat16_as_ushort(hy) << 16);
    lo = (uint32_t)__bfloat16_as_ushort(__float2bfloat16(rx)) |
         ((uint32_t)__bfloat16_as_ushort(__float2bfloat16(ry)) << 16);
}

// ---------------------------------------------------------------------------
// prep: rows [base*256, ...): B[n][k] hi/lo split of [Wl|Wr]
// ---------------------------------------------------------------------------
__global__ void prep_b(const float* __restrict__ Wl, const float* __restrict__ Wr,
                       int base) {
    int idx = (base + blockIdx.x) * 256 + threadIdx.x;
    int n = idx >> 9, k = idx & 511;
    float w = (k < 256) ? Wl[n * 256 + k] : Wr[n * 256 + (k - 256)];
    __nv_bfloat16 h = __float2bfloat16(w);
    float r = w - __bfloat162float(h);
    ((unsigned short*)g_Bhi)[idx] = __bfloat16_as_ushort(h);
    ((unsigned short*)g_Blo)[idx] = __bfloat16_as_ushort(__float2bfloat16(r));
}

// ---------------------------------------------------------------------------
struct ARegs { float4 a0, a1, b0, b1, d0, d1; };

__device__ __forceinline__ void load_A(int c, const float* __restrict__ childs,
                                       int p0, int tid, ARegs& ar) {
    const bool left = (c < 8);
    const int row = tid >> 2, cblk = tid & 3;
    const int j0 = (left ? c * 32 : (c - 8) * 32) + cblk * 8;
    const int o0 = left ? 0 : 256;
    const float* cb = childs + (size_t)(p0 + row) * 1024 + j0;
    ar.a0 = *(const float4*)(cb + o0);
    ar.a1 = *(const float4*)(cb + o0 + 4);
    ar.b0 = *(const float4*)(cb + o0 + 256);
    ar.b1 = *(const float4*)(cb + o0 + 260);
    ar.d0 = *(const float4*)(cb + o0 + 512);
    ar.d1 = *(const float4*)(cb + o0 + 516);
}

__device__ __forceinline__ void store_A(int c, const ARegs& ar, char* st, int tid) {
    const bool left = (c < 8);
    const float w0 = left ? 1.0f : (1.0f / 3.0f);
    const float w1 = 2.0f / 3.0f;
    const float w2 = left ? (1.0f / 3.0f) : 1.0f;
    float g0 = w0 * ar.a0.x + w1 * ar.b0.x + w2 * ar.d0.x;
    float g1 = w0 * ar.a0.y + w1 * ar.b0.y + w2 * ar.d0.y;
    float g2 = w0 * ar.a0.z + w1 * ar.b0.z + w2 * ar.d0.z;
    float g3 = w0 * ar.a0.w + w1 * ar.b0.w + w2 * ar.d0.w;
    float g4 = w0 * ar.a1.x + w1 * ar.b1.x + w2 * ar.d1.x;
    float g5 = w0 * ar.a1.y + w1 * ar.b1.y + w2 * ar.d1.y;
    float g6 = w0 * ar.a1.z + w1 * ar.b1.z + w2 * ar.d1.z;
    float g7 = w0 * ar.a1.w + w1 * ar.b1.w + w2 * ar.d1.w;
    uint4 uh, ul;
    split2(g0, g1, uh.x, ul.x);
    split2(g2, g3, uh.y, ul.y);
    split2(g4, g5, uh.z, ul.z);
    split2(g6, g7, uh.w, ul.w);
    const int row = tid >> 2, cblk = tid & 3;
    uint32_t sw = SW(row, cblk);
    *(uint4*)(st + ST_A_HI + sw) = uh;
    *(uint4*)(st + ST_A_LO + sw) = ul;
}

__device__ __forceinline__ void fill_B_async(uint32_t stage, int c, int n0, int tid) {
#pragma unroll
    for (int it = 0; it < 2; it++) {
        int idx  = it * 256 + tid;
        int row  = idx >> 2, cblk = idx & 3;
        int gi   = (n0 + row) * 64 + c * 4 + cblk;
        uint32_t sw = SW(row, cblk);
        cp_async16(stage + ST_B_HI + sw, g_Bhi + gi);
        cp_async16(stage + ST_B_LO + sw, g_Blo + gi);
    }
}

// ---------------------------------------------------------------------------
// HMMA level kernel. grid (n_par/64, 2, ksplit); chunks [z*nc, z*nc+nc).
// ksplit==1: fused +v/tanh to out.
// ksplit>1: fp32 partial to part + z*zstride; last CTA of tile reduces,
//           applies +v/tanh, writes out, resets its counter.
// ---------------------------------------------------------------------------
__global__ void __launch_bounds__(256, 2) level_mma(
    const float* __restrict__ childs,
    const float* __restrict__ vecs,
    float* __restrict__ out,
    float* __restrict__ part,
    int nc, size_t zstride)
{
    extern __shared__ char smem[];
    __shared__ int s_last;
    const uint32_t sbase = smem_u32(smem);
    const int tid  = threadIdx.x;
    const int warp = tid >> 5;
    const int lane = tid & 31;
    const int wm   = warp & 1;
    const int wn   = warp >> 1;
    const int p0   = blockIdx.x * MTILE;
    const int n0   = blockIdx.y * NTILE;
    const int c0   = blockIdx.z * nc;

    float acc[2][4][4];
#pragma unroll
    for (int i = 0; i < 2; i++)
#pragma unroll
        for (int j = 0; j < 4; j++)
#pragma unroll
            for (int q = 0; q < 4; q++) acc[i][j][q] = 0.0f;

    ARegs ar;
    load_A(c0, childs, p0, tid, ar);
    fill_B_async(sbase, c0, n0, tid);
    CP_COMMIT();
    store_A(c0, ar, smem, tid);

    for (int i = 0; i < nc; i++) {
        const int c = c0 + i;
        const int s = i & 1;
        CP_WAIT0();
        __syncthreads();

        const bool more = (i + 1 < nc);
        if (more) {
            load_A(c + 1, childs, p0, tid, ar);
            fill_B_async(sbase + (s ^ 1) * STAGE, c + 1, n0, tid);
            CP_COMMIT();
        }

        const uint32_t sA = sbase + s * STAGE;
#pragma unroll
        for (int ks = 0; ks < 2; ks++) {
            const int acb = ks * 2 + (lane >> 4);
            uint32_t ah[2][4], al[2][4];
            const int arow = wm * 32 + (lane & 15);
#pragma unroll
            for (int mi = 0; mi < 2; mi++) {
                uint32_t ad = sA + ST_A_HI + SW(arow + mi * 16, acb);
                ldsm_x4(ah[mi], ad);
                ldsm_x4(al[mi], ad + (ST_A_LO - ST_A_HI));
            }
#pragma unroll
            for (int nq = 0; nq < 2; nq++) {
                const int brow = wn * 32 + nq * 16 + (lane & 15);
                uint32_t bd = sA + ST_B_HI + SW(brow, acb);
                uint32_t qh[4], ql[4];
                ldsm_x4(qh, bd);
                ldsm_x4(ql, bd + (ST_B_LO - ST_B_HI));
                uint32_t bh0[2] = {qh[0], qh[2]}, bh1[2] = {qh[1], qh[3]};
                uint32_t bl0[2] = {ql[0], ql[2]}, bl1[2] = {ql[1], ql[3]};
#pragma unroll
                for (int mi = 0; mi < 2; mi++) {
                    mma16816(acc[mi][nq * 2],     ah[mi], bh0);
                    mma16816(acc[mi][nq * 2],     al[mi], bh0);
                    mma16816(acc[mi][nq * 2],     ah[mi], bl0);
                    mma16816(acc[mi][nq * 2 + 1], ah[mi], bh1);
                    mma16816(acc[mi][nq * 2 + 1], al[mi], bh1);
                    mma16816(acc[mi][nq * 2 + 1], ah[mi], bl1);
                }
            }
        }
        if (more) store_A(c + 1, ar, smem + (s ^ 1) * STAGE, tid);
        __syncthreads();
    }

    // ---- epilogue ----
    if (gridDim.z == 1) {
#pragma unroll
        for (int mi = 0; mi < 2; mi++) {
            const int r0 = p0 + wm * 32 + mi * 16 + (lane >> 2);
            const int r1 = r0 + 8;
#pragma unroll
            for (int nj = 0; nj < 4; nj++) {
                const int col = n0 + wn * 32 + nj * 8 + (lane & 3) * 2;
                float2 v0 = *(const float2*)(vecs + (size_t)r0 * 256 + col);
                float2 v1 = *(const float2*)(vecs + (size_t)r1 * 256 + col);
                float2 q0, q1;
                q0.x = tanhf(acc[mi][nj][0] + v0.x);
                q0.y = tanhf(acc[mi][nj][1] + v0.y);
                q1.x = tanhf(acc[mi][nj][2] + v1.x);
                q1.y = tanhf(acc[mi][nj][3] + v1.y);
                *(float2*)(out + (size_t)r0 * 256 + col) = q0;
                *(float2*)(out + (size_t)r1 * 256 + col) = q1;
            }
        }
    } else {
        // write fp32 partial for this z
        float* pz = part + (size_t)blockIdx.z * zstride;
#pragma unroll
        for (int mi = 0; mi < 2; mi++) {
            const int r0 = p0 + wm * 32 + mi * 16 + (lane >> 2);
            const int r1 = r0 + 8;
#pragma unroll
            for (int nj = 0; nj < 4; nj++) {
                const int col = n0 + wn * 32 + nj * 8 + (lane & 3) * 2;
                *(float2*)(pz + (size_t)r0 * 256 + col) =
                    make_float2(acc[mi][nj][0], acc[mi][nj][1]);
                *(float2*)(pz + (size_t)r1 * 256 + col) =
                    make_float2(acc[mi][nj][2], acc[mi][nj][3]);
            }
        }
        __threadfence();
        __syncthreads();
        const int tile = blockIdx.y * gridDim.x + blockIdx.x;
        if (tid == 0) {
            int old = atomicAdd(&g_cnt[tile], 1);
            s_last = (old == (int)gridDim.z - 1);
        }
        __syncthreads();
        if (s_last) {
            const int nz = gridDim.z;
            // tile = rows [p0,p0+64) x cols [n0,n0+128): 2048 float4s
            for (int idx = tid; idx < 2048; idx += 256) {
                const int row = idx >> 5;
                const int c4  = (idx & 31) * 4;
                const size_t o = (size_t)(p0 + row) * 256 + n0 + c4;
                float4 s = *(const float4*)(part + o);
                for (int z = 1; z < nz; z++) {
                    float4 t = *(const float4*)(part + (size_t)z * zstride + o);
                    s.x += t.x; s.y += t.y; s.z += t.z; s.w += t.w;
                }
                float4 v = *(const float4*)(vecs + o);
                float4 r;
                r.x = tanhf(s.x + v.x);
                r.y = tanhf(s.y + v.y);
                r.z = tanhf(s.z + v.z);
                r.w = tanhf(s.w + v.w);
                *(float4*)(out + o) = r;
            }
            if (tid == 0) g_cnt[tile] = 0;   // reset for next use / replay
        }
    }
}

// ---------------------------------------------------------------------------
// Small-level fp32 kernel: grid = n_par*8, 256 thr = 32 cols x 8 K-slices.
// ---------------------------------------------------------------------------
__global__ void __launch_bounds__(256) level_small(
    const float* __restrict__ childs,
    const float* __restrict__ Wl,
    const float* __restrict__ Wr,
    const float* __restrict__ vecs,
    float* __restrict__ out)
{
    __shared__ float G[512];
    __shared__ float part[8][33];
    const int tid = threadIdx.x;
    const int p   = blockIdx.x >> 3;
    const int cg  = blockIdx.x & 7;
    const float c23 = 2.0f / 3.0f, c13 = 1.0f / 3.0f;

    {
        const float* cb = childs + (size_t)p * 1024;
        int j = tid;
        G[j] = cb[j] + c23 * cb[256 + j] + c13 * cb[512 + j];
        G[256 + j] = c13 * cb[256 + j] + c23 * cb[512 + j] + cb[768 + j];
    }
    __syncthreads();

    const int cc = tid & 31;
    const int kg = tid >> 5;
    const int n  = cg * 32 + cc;
    const float* src = (kg < 4) ? (Wl + (size_t)n * 256 + kg * 64)
                                : (Wr + (size_t)n * 256 + (kg - 4) * 64);
    const float* g = G + kg * 64;

    float a0 = 0.f, a1 = 0.f, a2 = 0.f, a3 = 0.f;
#pragma unroll
    for (int i = 0; i < 64; i += 4) {
        float4 w = *(const float4*)(src + i);
        float4 gg = *(const float4*)(g + i);
        a0 = fmaf(gg.x, w.x, a0);
        a1 = fmaf(gg.y, w.y, a1);
        a2 = fmaf(gg.z, w.z, a2);
        a3 = fmaf(gg.w, w.w, a3);
    }
    part[kg][cc] = (a0 + a1) + (a2 + a3);
    __syncthreads();

    if (tid < 32) {
        float s = 0.f;
#pragma unroll
        for (int k = 0; k < 8; k++) s += part[k][tid];
        const int col = cg * 32 + tid;
        out[(size_t)p * 256 + col] = tanhf(s + vecs[(size_t)p * 256 + col]);
    }
}

// ---------------------------------------------------------------------------
extern "C" void kernel_launch(void* const* d_in, const int* in_sizes, int n_in,
                              void* d_out, int out_size) {
    const float* vectors = (const float*)d_in[0];
    const float* Wl = (const float*)d_in[1];
    const float* Wr = (const float*)d_in[2];

    static float* h0 = nullptr;
    static float* h1 = nullptr;
    static float* part = nullptr;
    static bool inited = false;
    if (!inited) {
        cudaGetSymbolAddress((void**)&h0, g_h0);
        cudaGetSymbolAddress((void**)&h1, g_h1);
        cudaGetSymbolAddress((void**)&part, g_part);
        cudaFuncSetAttribute(level_mma,
                             cudaFuncAttributeMaxDynamicSharedMemorySize, SMEM_REQ);
        inited = true;
    }

    // 3 prep launches (row ranges) => l7 lands at ncu capture slot (index 3)
    prep_b<<<171, 256>>>(Wl, Wr, 0);
    prep_b<<<171, 256>>>(Wl, Wr, 171);
    prep_b<<<170, 256>>>(Wl, Wr, 342);

    const float* cur = vectors + (size_t)21845 * 256;   // leaves (level 8)
    for (int l = 7; l >= 0; l--) {
        int n_par = 1 << (2 * l);
        size_t off = (size_t)(((1u << (2 * l)) - 1u) / 3u);
        const float* vecs = vectors + off * 256;
        float* out = (l == 0) ? (float*)d_out : ((l & 1) ? h0 : h1);
        if (n_par >= 16384) {
            level_mma<<<dim3(n_par / MTILE, 2, 1), 256, SMEM_REQ>>>(
                cur, vecs, out, part, 16, 0);
        } else if (n_par >= 1024) {
            int ksplit = (n_par >= 4096) ? 2 : 4;
            size_t zs = (size_t)n_par * 256;
            level_mma<<<dim3(n_par / MTILE, 2, ksplit), 256, SMEM_REQ>>>(
                cur, vecs, out, part, 16 / ksplit, zs);
        } else {
            level_small<<<n_par * 8, 256>>>(cur, Wl, Wr, vecs, out);
        }
        cur = out;
    }
}

// round 10
// speedup vs baseline: 1.0492x; 1.0492x over previous
#include <cuda_runtime.h>
#include <cuda_bf16.h>
#include <math.h>
#include <stdint.h>

// ===========================================================================
// CBTree B=4, L=9, d=256.
// h_par = tanh(G @ B^T + v),  G=[gl|gr] (M x 512),  B=[Wl|Wr] (256 x 512).
//   gl = c0 + (2/3)c1 + (1/3)c2 ;  gr = (1/3)c1 + (2/3)c2 + c3
// n_par>=1024: bf16 hi/lo 3-pass HMMA, CTA 64x128, cp.async 2-stage pipeline,
//   hoisted addressing, 1 barrier/chunk. Mid levels K-split + reduce kernel.
// n_par<=256: fp32 SIMT, grid n_par*8.
// ===========================================================================

#define MTILE 64
#define NTILE 128

#define ST_A_HI 0
#define ST_A_LO 4096
#define ST_B_HI 8192
#define ST_B_LO 16384
#define STAGE   24576
#define SMEM_REQ (2 * STAGE)  // 48 KB

#define SW(r, cb) ((uint32_t)((r) * 64 + (((cb) ^ (((r) >> 1) & 3)) << 4)))

__device__ float g_h0[16384 * 256];      // 16 MB ping
__device__ float g_h1[16384 * 256];      // 16 MB pong
__device__ float g_part[2097152];        // 8 MB K-split partials
__device__ uint4 g_Bhi[256 * 512 / 8];   // bf16 [256][512] hi of [Wl|Wr]
__device__ uint4 g_Blo[256 * 512 / 8];   // bf16 [256][512] lo

// ---------------------------------------------------------------------------
__device__ __forceinline__ uint32_t smem_u32(const void* p) {
    uint32_t a;
    asm("{ .reg .u64 t; cvta.to.shared.u64 t, %1; cvt.u32.u64 %0, t; }"
        : "=r"(a) : "l"(p));
    return a;
}
__device__ __forceinline__ void ldsm_x4(uint32_t* r, uint32_t addr) {
    asm volatile("ldmatrix.sync.aligned.m8n8.x4.shared.b16 {%0,%1,%2,%3}, [%4];"
                 : "=r"(r[0]), "=r"(r[1]), "=r"(r[2]), "=r"(r[3]) : "r"(addr));
}
__device__ __forceinline__ void mma16816(float* d, const uint32_t* a,
                                         const uint32_t* b) {
    asm volatile(
        "mma.sync.aligned.m16n8k16.row.col.f32.bf16.bf16.f32 "
        "{%0,%1,%2,%3}, {%4,%5,%6,%7}, {%8,%9}, {%0,%1,%2,%3};"
        : "+f"(d[0]), "+f"(d[1]), "+f"(d[2]), "+f"(d[3])
        : "r"(a[0]), "r"(a[1]), "r"(a[2]), "r"(a[3]), "r"(b[0]), "r"(b[1]));
}
__device__ __forceinline__ void cp_async16(uint32_t dst, const void* src) {
    asm volatile("cp.async.cg.shared.global [%0], [%1], 16;"
                 :: "r"(dst), "l"(src) : "memory");
}
#define CP_COMMIT() asm volatile("cp.async.commit_group;" ::: "memory")
#define CP_WAIT0()  asm volatile("cp.async.wait_group 0;" ::: "memory")

__device__ __forceinline__ void split2(float x, float y, uint32_t& hi, uint32_t& lo) {
    __nv_bfloat16 hx = __float2bfloat16(x);
    __nv_bfloat16 hy = __float2bfloat16(y);
    float rx = x - __bfloat162float(hx);
    float ry = y - __bfloat162float(hy);
    hi = (uint32_t)__bfloat16_as_ushort(hx) |
         ((uint32_t)__bfloat16_as_ushort(hy) << 16);
    lo = (uint32_t)__bfloat16_as_ushort(__float2bfloat16(rx)) |
         ((uint32_t)__bfloat16_as_ushort(__float2bfloat16(ry)) << 16);
}

// ---------------------------------------------------------------------------
__global__ void prep_b(const float* __restrict__ Wl, const float* __restrict__ Wr,
                       int base) {
    int idx = (base + blockIdx.x) * 256 + threadIdx.x;
    int n = idx >> 9, k = idx & 511;
    float w = (k < 256) ? Wl[n * 256 + k] : Wr[n * 256 + (k - 256)];
    __nv_bfloat16 h = __float2bfloat16(w);
    float r = w - __bfloat162float(h);
    ((unsigned short*)g_Bhi)[idx] = __bfloat16_as_ushort(h);
    ((unsigned short*)g_Blo)[idx] = __bfloat16_as_ushort(__float2bfloat16(r));
}

// ---------------------------------------------------------------------------
// HMMA level kernel. grid (n_par/64, 2, ksplit); chunks [z*nc, z*nc+nc).
// gridDim.z==1: fused +v/tanh.  else: fp32 partial to part + z*zstride.
// ---------------------------------------------------------------------------
__global__ void __launch_bounds__(256, 2) level_mma(
    const float* __restrict__ childs,
    const float* __restrict__ vecs,
    float* __restrict__ out,
    float* __restrict__ part,
    int nc, size_t zstride)
{
    extern __shared__ char smem[];
    const uint32_t sbase = smem_u32(smem);
    const int tid  = threadIdx.x;
    const int warp = tid >> 5;
    const int lane = tid & 31;
    const int wm   = warp & 1;
    const int wn   = warp >> 1;
    const int p0   = blockIdx.x * MTILE;
    const int n0   = blockIdx.y * NTILE;
    const int c0   = blockIdx.z * nc;

    // ---- hoisted fill-side addressing ----
    const int frow = tid >> 2, fcb = tid & 3;
    const uint32_t bsw0 = SW(frow, fcb);           // B row  frow
    const uint32_t bsw1 = SW(64 + frow, fcb);      // B row  64+frow
    const int gi0 = (n0 + frow) * 64 + fcb;
    const int gi1 = (n0 + 64 + frow) * 64 + fcb;
    const uint32_t asw = bsw0;                     // A store offset (row frow)
    const float* cbbase = childs + (size_t)(p0 + frow) * 1024 + fcb * 8;

    // ---- hoisted ldsm addressing (stage 0 base; +s*STAGE in loop) ----
    uint32_t aAddr[2][2], bAddr[2][2];
#pragma unroll
    for (int ks = 0; ks < 2; ks++) {
        const int acb = ks * 2 + (lane >> 4);
        const int arow = wm * 32 + (lane & 15);
#pragma unroll
        for (int mi = 0; mi < 2; mi++)
            aAddr[ks][mi] = sbase + ST_A_HI + SW(arow + mi * 16, acb);
#pragma unroll
        for (int nq = 0; nq < 2; nq++) {
            const int brow = wn * 32 + nq * 16 + (lane & 15);
            bAddr[ks][nq] = sbase + ST_B_HI + SW(brow, acb);
        }
    }

    float acc[2][4][4];
#pragma unroll
    for (int i = 0; i < 2; i++)
#pragma unroll
        for (int j = 0; j < 4; j++)
#pragma unroll
            for (int q = 0; q < 4; q++) acc[i][j][q] = 0.0f;

    float4 ra0, ra1, rb0, rb1, rd0, rd1;   // child regs for next chunk

    // ---- fill helpers (lambdas keep hoisted state in scope) ----
    auto load_A = [&](int c) {
        const bool left = (c < 8);
        const float* cb = cbbase + (left ? c * 32 : ((c - 8) * 32 + 256));
        ra0 = *(const float4*)(cb);
        ra1 = *(const float4*)(cb + 4);
        rb0 = *(const float4*)(cb + 256);
        rb1 = *(const float4*)(cb + 260);
        rd0 = *(const float4*)(cb + 512);
        rd1 = *(const float4*)(cb + 516);
    };
    auto store_A = [&](int c, uint32_t stOff) {
        const bool left = (c < 8);
        const float w0 = left ? 1.0f : (1.0f / 3.0f);
        const float w1 = 2.0f / 3.0f;
        const float w2 = left ? (1.0f / 3.0f) : 1.0f;
        float g0 = w0 * ra0.x + w1 * rb0.x + w2 * rd0.x;
        float g1 = w0 * ra0.y + w1 * rb0.y + w2 * rd0.y;
        float g2 = w0 * ra0.z + w1 * rb0.z + w2 * rd0.z;
        float g3 = w0 * ra0.w + w1 * rb0.w + w2 * rd0.w;
        float g4 = w0 * ra1.x + w1 * rb1.x + w2 * rd1.x;
        float g5 = w0 * ra1.y + w1 * rb1.y + w2 * rd1.y;
        float g6 = w0 * ra1.z + w1 * rb1.z + w2 * rd1.z;
        float g7 = w0 * ra1.w + w1 * rb1.w + w2 * rd1.w;
        uint4 uh, ul;
        split2(g0, g1, uh.x, ul.x);
        split2(g2, g3, uh.y, ul.y);
        split2(g4, g5, uh.z, ul.z);
        split2(g6, g7, uh.w, ul.w);
        char* st = smem + stOff;
        *(uint4*)(st + ST_A_HI + asw) = uh;
        *(uint4*)(st + ST_A_LO + asw) = ul;
    };
    auto fill_B = [&](int c, uint32_t stOff) {
        const uint32_t st = sbase + stOff;
        cp_async16(st + ST_B_HI + bsw0, g_Bhi + gi0 + c * 4);
        cp_async16(st + ST_B_LO + bsw0, g_Blo + gi0 + c * 4);
        cp_async16(st + ST_B_HI + bsw1, g_Bhi + gi1 + c * 4);
        cp_async16(st + ST_B_LO + bsw1, g_Blo + gi1 + c * 4);
    };

    // prologue: chunk c0 -> stage 0
    load_A(c0);
    fill_B(c0, 0);
    CP_COMMIT();
    store_A(c0, 0);

    for (int i = 0; i < nc; i++) {
        const int c = c0 + i;
        const uint32_t sOff = (i & 1) ? STAGE : 0;
        const uint32_t sOffN = sOff ^ STAGE;
        CP_WAIT0();
        __syncthreads();   // stage ready: B arrived, A stored, prev readers done

        const bool more = (i + 1 < nc);
        if (more) {
            load_A(c + 1);
            fill_B(c + 1, sOffN);
            CP_COMMIT();
        }

#pragma unroll
        for (int ks = 0; ks < 2; ks++) {
            uint32_t ah[2][4], al[2][4];
#pragma unroll
            for (int mi = 0; mi < 2; mi++) {
                const uint32_t ad = aAddr[ks][mi] + sOff;
                ldsm_x4(ah[mi], ad);
                ldsm_x4(al[mi], ad + (ST_A_LO - ST_A_HI));
            }
#pragma unroll
            for (int nq = 0; nq < 2; nq++) {
                const uint32_t bd = bAddr[ks][nq] + sOff;
                uint32_t qh[4], ql[4];
                ldsm_x4(qh, bd);
                ldsm_x4(ql, bd + (ST_B_LO - ST_B_HI));
                uint32_t bh0[2] = {qh[0], qh[2]}, bh1[2] = {qh[1], qh[3]};
                uint32_t bl0[2] = {ql[0], ql[2]}, bl1[2] = {ql[1], ql[3]};
#pragma unroll
                for (int mi = 0; mi < 2; mi++) {
                    mma16816(acc[mi][nq * 2],     ah[mi], bh0);
                    mma16816(acc[mi][nq * 2],     al[mi], bh0);
                    mma16816(acc[mi][nq * 2],     ah[mi], bl0);
                    mma16816(acc[mi][nq * 2 + 1], ah[mi], bh1);
                    mma16816(acc[mi][nq * 2 + 1], al[mi], bh1);
                    mma16816(acc[mi][nq * 2 + 1], ah[mi], bl1);
                }
            }
        }
        if (more) store_A(c + 1, sOffN);
        // no trailing barrier: next iteration's leading barrier orders reuse
    }

    // ---- epilogue ----
    float* dst = (gridDim.z == 1) ? out : (part + (size_t)blockIdx.z * zstride);
    const bool fused = (gridDim.z == 1);
#pragma unroll
    for (int mi = 0; mi < 2; mi++) {
        const int r0 = p0 + wm * 32 + mi * 16 + (lane >> 2);
        const int r1 = r0 + 8;
#pragma unroll
        for (int nj = 0; nj < 4; nj++) {
            const int col = n0 + wn * 32 + nj * 8 + (lane & 3) * 2;
            if (fused) {
                float2 v0 = *(const float2*)(vecs + (size_t)r0 * 256 + col);
                float2 v1 = *(const float2*)(vecs + (size_t)r1 * 256 + col);
                float2 q0, q1;
                q0.x = tanhf(acc[mi][nj][0] + v0.x);
                q0.y = tanhf(acc[mi][nj][1] + v0.y);
                q1.x = tanhf(acc[mi][nj][2] + v1.x);
                q1.y = tanhf(acc[mi][nj][3] + v1.y);
                *(float2*)(dst + (size_t)r0 * 256 + col) = q0;
                *(float2*)(dst + (size_t)r1 * 256 + col) = q1;
            } else {
                *(float2*)(dst + (size_t)r0 * 256 + col) =
                    make_float2(acc[mi][nj][0], acc[mi][nj][1]);
                *(float2*)(dst + (size_t)r1 * 256 + col) =
                    make_float2(acc[mi][nj][2], acc[mi][nj][3]);
            }
        }
    }
}

// ---------------------------------------------------------------------------
__global__ void __launch_bounds__(256) reduce_tanh(
    const float* __restrict__ part, const float* __restrict__ vecs,
    float* __restrict__ out, int nsplit, size_t zstride)
{
    size_t i = (size_t)blockIdx.x * 256 + threadIdx.x;   // float4 index
    float4 s = ((const float4*)part)[i];
    for (int z = 1; z < nsplit; z++) {
        float4 t = *(const float4*)(part + z * zstride + i * 4);
        s.x += t.x; s.y += t.y; s.z += t.z; s.w += t.w;
    }
    float4 v = ((const float4*)vecs)[i];
    float4 r;
    r.x = tanhf(s.x + v.x);
    r.y = tanhf(s.y + v.y);
    r.z = tanhf(s.z + v.z);
    r.w = tanhf(s.w + v.w);
    ((float4*)out)[i] = r;
}

// ---------------------------------------------------------------------------
__global__ void __launch_bounds__(256) level_small(
    const float* __restrict__ childs,
    const float* __restrict__ Wl,
    const float* __restrict__ Wr,
    const float* __restrict__ vecs,
    float* __restrict__ out)
{
    __shared__ float G[512];
    __shared__ float part[8][33];
    const int tid = threadIdx.x;
    const int p   = blockIdx.x >> 3;
    const int cg  = blockIdx.x & 7;
    const float c23 = 2.0f / 3.0f, c13 = 1.0f / 3.0f;

    {
        const float* cb = childs + (size_t)p * 1024;
        int j = tid;
        G[j] = cb[j] + c23 * cb[256 + j] + c13 * cb[512 + j];
        G[256 + j] = c13 * cb[256 + j] + c23 * cb[512 + j] + cb[768 + j];
    }
    __syncthreads();

    const int cc = tid & 31;
    const int kg = tid >> 5;
    const int n  = cg * 32 + cc;
    const float* src = (kg < 4) ? (Wl + (size_t)n * 256 + kg * 64)
                                : (Wr + (size_t)n * 256 + (kg - 4) * 64);
    const float* g = G + kg * 64;

    float a0 = 0.f, a1 = 0.f, a2 = 0.f, a3 = 0.f;
#pragma unroll
    for (int i = 0; i < 64; i += 4) {
        float4 w = *(const float4*)(src + i);
        float4 gg = *(const float4*)(g + i);
        a0 = fmaf(gg.x, w.x, a0);
        a1 = fmaf(gg.y, w.y, a1);
        a2 = fmaf(gg.z, w.z, a2);
        a3 = fmaf(gg.w, w.w, a3);
    }
    part[kg][cc] = (a0 + a1) + (a2 + a3);
    __syncthreads();

    if (tid < 32) {
        float s = 0.f;
#pragma unroll
        for (int k = 0; k < 8; k++) s += part[k][tid];
        const int col = cg * 32 + tid;
        out[(size_t)p * 256 + col] = tanhf(s + vecs[(size_t)p * 256 + col]);
    }
}

// ---------------------------------------------------------------------------
extern "C" void kernel_launch(void* const* d_in, const int* in_sizes, int n_in,
                              void* d_out, int out_size) {
    const float* vectors = (const float*)d_in[0];
    const float* Wl = (const float*)d_in[1];
    const float* Wr = (const float*)d_in[2];

    static float* h0 = nullptr;
    static float* h1 = nullptr;
    static float* part = nullptr;
    static bool inited = false;
    if (!inited) {
        cudaGetSymbolAddress((void**)&h0, g_h0);
        cudaGetSymbolAddress((void**)&h1, g_h1);
        cudaGetSymbolAddress((void**)&part, g_part);
        cudaFuncSetAttribute(level_mma,
                             cudaFuncAttributeMaxDynamicSharedMemorySize, SMEM_REQ);
        inited = true;
    }

    // 3 prep launches => l7 stays at ncu capture slot (index 3)
    prep_b<<<171, 256>>>(Wl, Wr, 0);
    prep_b<<<171, 256>>>(Wl, Wr, 171);
    prep_b<<<170, 256>>>(Wl, Wr, 342);

    const float* cur = vectors + (size_t)21845 * 256;   // leaves (level 8)
    for (int l = 7; l >= 0; l--) {
        int n_par = 1 << (2 * l);
        size_t off = (size_t)(((1u << (2 * l)) - 1u) / 3u);
        const float* vecs = vectors + off * 256;
        float* out = (l == 0) ? (float*)d_out : ((l & 1) ? h0 : h1);
        if (n_par >= 16384) {
            level_mma<<<dim3(n_par / MTILE, 2, 1), 256, SMEM_REQ>>>(
                cur, vecs, out, part, 16, 0);
        } else if (n_par >= 1024) {
            int ksplit = (n_par >= 4096) ? 2 : 4;
            size_t zs = (size_t)n_par * 256;
            level_mma<<<dim3(n_par / MTILE, 2, ksplit), 256, SMEM_REQ>>>(
                cur, nullptr, out, part, 16 / ksplit, zs);
            reduce_tanh<<<(unsigned)(zs / 1024), 256>>>(part, vecs, out, ksplit, zs);
        } else {
            level_small<<<n_par * 8, 256>>>(cur, Wl, Wr, vecs, out);
        }
        cur = out;
    }
}

// round 11
// speedup vs baseline: 1.1317x; 1.0786x over previous
#include <cuda_runtime.h>
#include <cuda_bf16.h>
#include <math.h>
#include <stdint.h>

// ===========================================================================
// CBTree B=4, L=9, d=256.
// h_par = tanh(G @ B^T + v),  G=[gl|gr] (M x 512),  B=[Wl|Wr] (256 x 512).
//   gl = c0 + (2/3)c1 + (1/3)c2 ;  gr = (1/3)c1 + (2/3)c2 + c3
// n_par>=1024: bf16 hi/lo 3-pass HMMA. CTA 64(M) x 256(N full), 512 thr,
//   16 warps (2Mx8N, warp 32x32), cp.async 2-stage, K-split + reduce kernel.
// n_par<=256: fp32 SIMT, grid n_par*8.
// ===========================================================================

#define MTILE 64

#define ST_A_HI 0
#define ST_A_LO 4096
#define ST_B_HI 8192
#define ST_B_LO 24576
#define STAGE   40960
#define SMEM_REQ (2 * STAGE)  // 80 KB

#define SW(r, cb) ((uint32_t)((r) * 64 + (((cb) ^ (((r) >> 1) & 3)) << 4)))

__device__ float g_h0[16384 * 256];      // 16 MB ping
__device__ float g_h1[16384 * 256];      // 16 MB pong
__device__ float g_part[2097152];        // 8 MB K-split partials
__device__ uint4 g_Bhi[256 * 512 / 8];   // bf16 [256][512] hi of [Wl|Wr]
__device__ uint4 g_Blo[256 * 512 / 8];   // bf16 [256][512] lo

// ---------------------------------------------------------------------------
__device__ __forceinline__ uint32_t smem_u32(const void* p) {
    uint32_t a;
    asm("{ .reg .u64 t; cvta.to.shared.u64 t, %1; cvt.u32.u64 %0, t; }"
        : "=r"(a) : "l"(p));
    return a;
}
__device__ __forceinline__ void ldsm_x4(uint32_t* r, uint32_t addr) {
    asm volatile("ldmatrix.sync.aligned.m8n8.x4.shared.b16 {%0,%1,%2,%3}, [%4];"
                 : "=r"(r[0]), "=r"(r[1]), "=r"(r[2]), "=r"(r[3]) : "r"(addr));
}
__device__ __forceinline__ void mma16816(float* d, const uint32_t* a,
                                         const uint32_t* b) {
    asm volatile(
        "mma.sync.aligned.m16n8k16.row.col.f32.bf16.bf16.f32 "
        "{%0,%1,%2,%3}, {%4,%5,%6,%7}, {%8,%9}, {%0,%1,%2,%3};"
        : "+f"(d[0]), "+f"(d[1]), "+f"(d[2]), "+f"(d[3])
        : "r"(a[0]), "r"(a[1]), "r"(a[2]), "r"(a[3]), "r"(b[0]), "r"(b[1]));
}
__device__ __forceinline__ void cp_async16(uint32_t dst, const void* src) {
    asm volatile("cp.async.cg.shared.global [%0], [%1], 16;"
                 :: "r"(dst), "l"(src) : "memory");
}
#define CP_COMMIT() asm volatile("cp.async.commit_group;" ::: "memory")
#define CP_WAIT0()  asm volatile("cp.async.wait_group 0;" ::: "memory")

__device__ __forceinline__ void split2(float x, float y, uint32_t& hi, uint32_t& lo) {
    __nv_bfloat16 hx = __float2bfloat16(x);
    __nv_bfloat16 hy = __float2bfloat16(y);
    float rx = x - __bfloat162float(hx);
    float ry = y - __bfloat162float(hy);
    hi = (uint32_t)__bfloat16_as_ushort(hx) |
         ((uint32_t)__bfloat16_as_ushort(hy) << 16);
    lo = (uint32_t)__bfloat16_as_ushort(__float2bfloat16(rx)) |
         ((uint32_t)__bfloat16_as_ushort(__float2bfloat16(ry)) << 16);
}

// ---------------------------------------------------------------------------
__global__ void prep_b(const float* __restrict__ Wl, const float* __restrict__ Wr,
                       int base) {
    int idx = (base + blockIdx.x) * 256 + threadIdx.x;
    int n = idx >> 9, k = idx & 511;
    float w = (k < 256) ? Wl[n * 256 + k] : Wr[n * 256 + (k - 256)];
    __nv_bfloat16 h = __float2bfloat16(w);
    float r = w - __bfloat162float(h);
    ((unsigned short*)g_Bhi)[idx] = __bfloat16_as_ushort(h);
    ((unsigned short*)g_Blo)[idx] = __bfloat16_as_ushort(__float2bfloat16(r));
}

// ---------------------------------------------------------------------------
// HMMA level kernel. grid (n_par/64, 1, ksplit); chunks [z*nc, z*nc+nc).
// CTA = 64(M) x 256(N). gridDim.z==1: fused +v/tanh, else partial to part.
// ---------------------------------------------------------------------------
__global__ void __launch_bounds__(512, 1) level_mma(
    const float* __restrict__ childs,
    const float* __restrict__ vecs,
    float* __restrict__ out,
    float* __restrict__ part,
    int nc, size_t zstride)
{
    extern __shared__ char smem[];
    const uint32_t sbase = smem_u32(smem);
    const int tid  = threadIdx.x;
    const int warp = tid >> 5;
    const int lane = tid & 31;
    const int wm   = warp & 1;          // M 32-block (0..1)
    const int wn   = warp >> 1;         // N 32-block (0..7)
    const int p0   = blockIdx.x * MTILE;
    const int c0   = blockIdx.z * nc;

    // ---- hoisted fill-side addressing ----
    // B: 256 rows x 4 cb = 1024 16B-pairs -> 2 per thread (rows fr, 128+fr)
    const int fr  = tid >> 2, fcb = tid & 3;
    const uint32_t bswA = SW(fr, fcb);
    const uint32_t bswB = SW(128 + fr, fcb);
    const int giA = fr * 64 + fcb;
    const int giB = (128 + fr) * 64 + fcb;
    // A: 64 rows x 4 cb = 256 pairs -> threads 0-255 only
    const bool aThread = (tid < 256);
    const uint32_t asw = bswA;                       // row fr (0..63), cb fcb
    const float* cbbase = childs + (size_t)(p0 + fr) * 1024 + fcb * 8;

    // ---- hoisted ldsm addressing (stage 0 base; +sOff in loop) ----
    uint32_t aAddr[2][2], bAddr[2][2];
#pragma unroll
    for (int ks = 0; ks < 2; ks++) {
        const int acb = ks * 2 + (lane >> 4);
        const int arow = wm * 32 + (lane & 15);
#pragma unroll
        for (int mi = 0; mi < 2; mi++)
            aAddr[ks][mi] = sbase + ST_A_HI + SW(arow + mi * 16, acb);
#pragma unroll
        for (int nq = 0; nq < 2; nq++) {
            const int brow = wn * 32 + nq * 16 + (lane & 15);
            bAddr[ks][nq] = sbase + ST_B_HI + SW(brow, acb);
        }
    }

    float acc[2][4][4];
#pragma unroll
    for (int i = 0; i < 2; i++)
#pragma unroll
        for (int j = 0; j < 4; j++)
#pragma unroll
            for (int q = 0; q < 4; q++) acc[i][j][q] = 0.0f;

    float4 ra0, ra1, rb0, rb1, rd0, rd1;   // child regs for next chunk (A threads)

    auto load_A = [&](int c) {
        if (!aThread) return;
        const bool left = (c < 8);
        const float* cb = cbbase + (left ? c * 32 : ((c - 8) * 32 + 256));
        ra0 = *(const float4*)(cb);
        ra1 = *(const float4*)(cb + 4);
        rb0 = *(const float4*)(cb + 256);
        rb1 = *(const float4*)(cb + 260);
        rd0 = *(const float4*)(cb + 512);
        rd1 = *(const float4*)(cb + 516);
    };
    auto store_A = [&](int c, uint32_t stOff) {
        if (!aThread) return;
        const bool left = (c < 8);
        const float w0 = left ? 1.0f : (1.0f / 3.0f);
        const float w1 = 2.0f / 3.0f;
        const float w2 = left ? (1.0f / 3.0f) : 1.0f;
        float g0 = w0 * ra0.x + w1 * rb0.x + w2 * rd0.x;
        float g1 = w0 * ra0.y + w1 * rb0.y + w2 * rd0.y;
        float g2 = w0 * ra0.z + w1 * rb0.z + w2 * rd0.z;
        float g3 = w0 * ra0.w + w1 * rb0.w + w2 * rd0.w;
        float g4 = w0 * ra1.x + w1 * rb1.x + w2 * rd1.x;
        float g5 = w0 * ra1.y + w1 * rb1.y + w2 * rd1.y;
        float g6 = w0 * ra1.z + w1 * rb1.z + w2 * rd1.z;
        float g7 = w0 * ra1.w + w1 * rb1.w + w2 * rd1.w;
        uint4 uh, ul;
        split2(g0, g1, uh.x, ul.x);
        split2(g2, g3, uh.y, ul.y);
        split2(g4, g5, uh.z, ul.z);
        split2(g6, g7, uh.w, ul.w);
        char* st = smem + stOff;
        *(uint4*)(st + ST_A_HI + asw) = uh;
        *(uint4*)(st + ST_A_LO + asw) = ul;
    };
    auto fill_B = [&](int c, uint32_t stOff) {
        const uint32_t st = sbase + stOff;
        const int cc = c * 4;
        cp_async16(st + ST_B_HI + bswA, g_Bhi + giA + cc);
        cp_async16(st + ST_B_LO + bswA, g_Blo + giA + cc);
        cp_async16(st + ST_B_HI + bswB, g_Bhi + giB + cc);
        cp_async16(st + ST_B_LO + bswB, g_Blo + giB + cc);
    };

    // prologue: chunk c0 -> stage 0
    load_A(c0);
    fill_B(c0, 0);
    CP_COMMIT();
    store_A(c0, 0);

    for (int i = 0; i < nc; i++) {
        const int c = c0 + i;
        const uint32_t sOff = (i & 1) ? STAGE : 0;
        const uint32_t sOffN = sOff ^ STAGE;
        CP_WAIT0();
        __syncthreads();   // stage ready: B arrived, A stored, prev readers done

        const bool more = (i + 1 < nc);
        if (more) {
            load_A(c + 1);
            fill_B(c + 1, sOffN);
            CP_COMMIT();
        }

#pragma unroll
        for (int ks = 0; ks < 2; ks++) {
            uint32_t ah[2][4], al[2][4];
#pragma unroll
            for (int mi = 0; mi < 2; mi++) {
                const uint32_t ad = aAddr[ks][mi] + sOff;
                ldsm_x4(ah[mi], ad);
                ldsm_x4(al[mi], ad + (ST_A_LO - ST_A_HI));
            }
#pragma unroll
            for (int nq = 0; nq < 2; nq++) {
                const uint32_t bd = bAddr[ks][nq] + sOff;
                uint32_t qh[4], ql[4];
                ldsm_x4(qh, bd);
                ldsm_x4(ql, bd + (ST_B_LO - ST_B_HI));
                uint32_t bh0[2] = {qh[0], qh[2]}, bh1[2] = {qh[1], qh[3]};
                uint32_t bl0[2] = {ql[0], ql[2]}, bl1[2] = {ql[1], ql[3]};
#pragma unroll
                for (int mi = 0; mi < 2; mi++) {
                    mma16816(acc[mi][nq * 2],     ah[mi], bh0);
                    mma16816(acc[mi][nq * 2],     al[mi], bh0);
                    mma16816(acc[mi][nq * 2],     ah[mi], bl0);
                    mma16816(acc[mi][nq * 2 + 1], ah[mi], bh1);
                    mma16816(acc[mi][nq * 2 + 1], al[mi], bh1);
                    mma16816(acc[mi][nq * 2 + 1], ah[mi], bl1);
                }
            }
        }
        if (more) store_A(c + 1, sOffN);
    }

    // ---- epilogue ----
    float* dst = (gridDim.z == 1) ? out : (part + (size_t)blockIdx.z * zstride);
    const bool fused = (gridDim.z == 1);
#pragma unroll
    for (int mi = 0; mi < 2; mi++) {
        const int r0 = p0 + wm * 32 + mi * 16 + (lane >> 2);
        const int r1 = r0 + 8;
#pragma unroll
        for (int nj = 0; nj < 4; nj++) {
            const int col = wn * 32 + nj * 8 + (lane & 3) * 2;
            if (fused) {
                float2 v0 = *(const float2*)(vecs + (size_t)r0 * 256 + col);
                float2 v1 = *(const float2*)(vecs + (size_t)r1 * 256 + col);
                float2 q0, q1;
                q0.x = tanhf(acc[mi][nj][0] + v0.x);
                q0.y = tanhf(acc[mi][nj][1] + v0.y);
                q1.x = tanhf(acc[mi][nj][2] + v1.x);
                q1.y = tanhf(acc[mi][nj][3] + v1.y);
                *(float2*)(dst + (size_t)r0 * 256 + col) = q0;
                *(float2*)(dst + (size_t)r1 * 256 + col) = q1;
            } else {
                *(float2*)(dst + (size_t)r0 * 256 + col) =
                    make_float2(acc[mi][nj][0], acc[mi][nj][1]);
                *(float2*)(dst + (size_t)r1 * 256 + col) =
                    make_float2(acc[mi][nj][2], acc[mi][nj][3]);
            }
        }
    }
}

// ---------------------------------------------------------------------------
__global__ void __launch_bounds__(256) reduce_tanh(
    const float* __restrict__ part, const float* __restrict__ vecs,
    float* __restrict__ out, int nsplit, size_t zstride)
{
    size_t i = (size_t)blockIdx.x * 256 + threadIdx.x;   // float4 index
    float4 s = ((const float4*)part)[i];
    for (int z = 1; z < nsplit; z++) {
        float4 t = *(const float4*)(part + z * zstride + i * 4);
        s.x += t.x; s.y += t.y; s.z += t.z; s.w += t.w;
    }
    float4 v = ((const float4*)vecs)[i];
    float4 r;
    r.x = tanhf(s.x + v.x);
    r.y = tanhf(s.y + v.y);
    r.z = tanhf(s.z + v.z);
    r.w = tanhf(s.w + v.w);
    ((float4*)out)[i] = r;
}

// ---------------------------------------------------------------------------
__global__ void __launch_bounds__(256) level_small(
    const float* __restrict__ childs,
    const float* __restrict__ Wl,
    const float* __restrict__ Wr,
    const float* __restrict__ vecs,
    float* __restrict__ out)
{
    __shared__ float G[512];
    __shared__ float part[8][33];
    const int tid = threadIdx.x;
    const int p   = blockIdx.x >> 3;
    const int cg  = blockIdx.x & 7;
    const float c23 = 2.0f / 3.0f, c13 = 1.0f / 3.0f;

    {
        const float* cb = childs + (size_t)p * 1024;
        int j = tid;
        G[j] = cb[j] + c23 * cb[256 + j] + c13 * cb[512 + j];
        G[256 + j] = c13 * cb[256 + j] + c23 * cb[512 + j] + cb[768 + j];
    }
    __syncthreads();

    const int cc = tid & 31;
    const int kg = tid >> 5;
    const int n  = cg * 32 + cc;
    const float* src = (kg < 4) ? (Wl + (size_t)n * 256 + kg * 64)
                                : (Wr + (size_t)n * 256 + (kg - 4) * 64);
    const float* g = G + kg * 64;

    float a0 = 0.f, a1 = 0.f, a2 = 0.f, a3 = 0.f;
#pragma unroll
    for (int i = 0; i < 64; i += 4) {
        float4 w = *(const float4*)(src + i);
        float4 gg = *(const float4*)(g + i);
        a0 = fmaf(gg.x, w.x, a0);
        a1 = fmaf(gg.y, w.y, a1);
        a2 = fmaf(gg.z, w.z, a2);
        a3 = fmaf(gg.w, w.w, a3);
    }
    part[kg][cc] = (a0 + a1) + (a2 + a3);
    __syncthreads();

    if (tid < 32) {
        float s = 0.f;
#pragma unroll
        for (int k = 0; k < 8; k++) s += part[k][tid];
        const int col = cg * 32 + tid;
        out[(size_t)p * 256 + col] = tanhf(s + vecs[(size_t)p * 256 + col]);
    }
}

// ---------------------------------------------------------------------------
extern "C" void kernel_launch(void* const* d_in, const int* in_sizes, int n_in,
                              void* d_out, int out_size) {
    const float* vectors = (const float*)d_in[0];
    const float* Wl = (const float*)d_in[1];
    const float* Wr = (const float*)d_in[2];

    static float* h0 = nullptr;
    static float* h1 = nullptr;
    static float* part = nullptr;
    static bool inited = false;
    if (!inited) {
        cudaGetSymbolAddress((void**)&h0, g_h0);
        cudaGetSymbolAddress((void**)&h1, g_h1);
        cudaGetSymbolAddress((void**)&part, g_part);
        cudaFuncSetAttribute(level_mma,
                             cudaFuncAttributeMaxDynamicSharedMemorySize, SMEM_REQ);
        inited = true;
    }

    // 3 prep launches => l7 stays at ncu capture slot (index 3)
    prep_b<<<171, 256>>>(Wl, Wr, 0);
    prep_b<<<171, 256>>>(Wl, Wr, 171);
    prep_b<<<170, 256>>>(Wl, Wr, 342);

    const float* cur = vectors + (size_t)21845 * 256;   // leaves (level 8)
    for (int l = 7; l >= 0; l--) {
        int n_par = 1 << (2 * l);
        size_t off = (size_t)(((1u << (2 * l)) - 1u) / 3u);
        const float* vecs = vectors + off * 256;
        float* out = (l == 0) ? (float*)d_out : ((l & 1) ? h0 : h1);
        if (n_par >= 16384) {
            level_mma<<<dim3(n_par / MTILE, 1, 1), 512, SMEM_REQ>>>(
                cur, vecs, out, part, 16, 0);
        } else if (n_par >= 1024) {
            int ksplit = (n_par >= 4096) ? 2 : 4;
            size_t zs = (size_t)n_par * 256;
            level_mma<<<dim3(n_par / MTILE, 1, ksplit), 512, SMEM_REQ>>>(
                cur, nullptr, out, part, 16 / ksplit, zs);
            reduce_tanh<<<(unsigned)(zs / 1024), 256>>>(part, vecs, out, ksplit, zs);
        } else {
            level_small<<<n_par * 8, 256>>>(cur, Wl, Wr, vecs, out);
        }
        cur = out;
    }
}